// round 1
// baseline (speedup 1.0000x reference)
#include <cuda_runtime.h>
#include <math.h>

#define T     4096
#define H     16
#define HKV   4
#define D     128
#define HID   2048
#define QKV_N ((H + 2 * HKV) * D)   // 3072
#define QD    (H * D)               // 2048
#define KD    (HKV * D)             // 512
#define EPSV  1e-5f

// Scratch (device globals: allocation-free per harness rules)
__device__ float g_qkv[T * QKV_N];   // [T, 3072]  q|k|v projection output
__device__ float g_q[T * QD];        // roped+normed q
__device__ float g_k[T * KD];        // roped+normed k
__device__ float g_attn[T * QD];     // attention output

// ---------------------------------------------------------------------------
// NT SGEMM: C[M,N] = A[M,K] * B[N,K]^T   (both row-major, K contiguous)
// 128x128 block tile, BK=8, 8x8 register tile, 256 threads.
// M,N,K all multiples of tile sizes for this problem (no bounds checks).
// ---------------------------------------------------------------------------
__global__ __launch_bounds__(256) void sgemm_nt(const float* __restrict__ A,
                                                const float* __restrict__ B,
                                                float* __restrict__ C,
                                                int M, int N, int K) {
    __shared__ float As[8][128];
    __shared__ float Bs[8][128];

    const int bm  = blockIdx.y * 128;
    const int bn  = blockIdx.x * 128;
    const int tid = threadIdx.x;
    const int tx  = tid % 16;
    const int ty  = tid / 16;

    float acc[8][8];
#pragma unroll
    for (int i = 0; i < 8; i++)
#pragma unroll
        for (int j = 0; j < 8; j++) acc[i][j] = 0.0f;

    const int lr = tid / 2;          // row within 128-row tile
    const int lc = (tid % 2) * 4;    // k-offset within 8-wide slab
    const float* Ap = A + (size_t)(bm + lr) * K + lc;
    const float* Bp = B + (size_t)(bn + lr) * K + lc;

    for (int k0 = 0; k0 < K; k0 += 8) {
        float4 av = *(const float4*)(Ap + k0);
        float4 bv = *(const float4*)(Bp + k0);
        As[lc + 0][lr] = av.x; As[lc + 1][lr] = av.y;
        As[lc + 2][lr] = av.z; As[lc + 3][lr] = av.w;
        Bs[lc + 0][lr] = bv.x; Bs[lc + 1][lr] = bv.y;
        Bs[lc + 2][lr] = bv.z; Bs[lc + 3][lr] = bv.w;
        __syncthreads();

#pragma unroll
        for (int kk = 0; kk < 8; kk++) {
            float a[8], b[8];
            *(float4*)&a[0] = *(const float4*)&As[kk][ty * 8];
            *(float4*)&a[4] = *(const float4*)&As[kk][ty * 8 + 4];
            *(float4*)&b[0] = *(const float4*)&Bs[kk][tx * 8];
            *(float4*)&b[4] = *(const float4*)&Bs[kk][tx * 8 + 4];
#pragma unroll
            for (int i = 0; i < 8; i++)
#pragma unroll
                for (int j = 0; j < 8; j++)
                    acc[i][j] = fmaf(a[i], b[j], acc[i][j]);
        }
        __syncthreads();
    }

#pragma unroll
    for (int i = 0; i < 8; i++) {
        float* Cp = C + (size_t)(bm + ty * 8 + i) * N + bn + tx * 8;
#pragma unroll
        for (int j = 0; j < 8; j++) Cp[j] = acc[i][j];
    }
}

// ---------------------------------------------------------------------------
// RoPE + RMSNorm for q (2048/row) and k (512/row). One CTA per token.
// ---------------------------------------------------------------------------
__global__ __launch_bounds__(256) void rope_norm_kernel(
    const int* __restrict__ positions,
    const float* __restrict__ qnw,
    const float* __restrict__ knw) {
    const int t   = blockIdx.x;
    const int tid = threadIdx.x;
    const float pos = (float)positions[t];

    __shared__ float row[QD];     // holds roped q (2048), later roped k (512)
    __shared__ float red[256];

    const float* base = g_qkv + (size_t)t * QKV_N;

    // ---- Q: rope then accumulate sum of squares ----
    float ss = 0.0f;
#pragma unroll
    for (int i = 0; i < QD / 256; i++) {
        int idx = tid + i * 256;
        int d   = idx & 127;
        int hb  = idx - d;             // h*128
        int fi  = d & 63;
        float inv = powf(10000.0f, -(float)(2 * fi) * (1.0f / 128.0f));
        float ang = pos * inv;
        float sv, cv;
        sincosf(ang, &sv, &cv);
        float v;
        if (d < 64) v = base[hb + d] * cv - base[hb + d + 64] * sv;
        else        v = base[hb + d] * cv + base[hb + d - 64] * sv;
        row[idx] = v;
        ss += v * v;
    }
    red[tid] = ss;
    __syncthreads();
    for (int s2 = 128; s2 > 0; s2 >>= 1) {
        if (tid < s2) red[tid] += red[tid + s2];
        __syncthreads();
    }
    float qscale = rsqrtf(red[0] * (1.0f / QD) + EPSV);
#pragma unroll
    for (int i = 0; i < QD / 256; i++) {
        int idx = tid + i * 256;
        g_q[(size_t)t * QD + idx] = row[idx] * qscale * qnw[idx];
    }
    __syncthreads();

    // ---- K: rope then rmsnorm over 512 ----
    const float* kbase = base + QD;
    float ssk = 0.0f;
#pragma unroll
    for (int i = 0; i < KD / 256; i++) {
        int idx = tid + i * 256;
        int d   = idx & 127;
        int hb  = idx - d;
        int fi  = d & 63;
        float inv = powf(10000.0f, -(float)(2 * fi) * (1.0f / 128.0f));
        float ang = pos * inv;
        float sv, cv;
        sincosf(ang, &sv, &cv);
        float v;
        if (d < 64) v = kbase[hb + d] * cv - kbase[hb + d + 64] * sv;
        else        v = kbase[hb + d] * cv + kbase[hb + d - 64] * sv;
        row[idx] = v;
        ssk += v * v;
    }
    red[tid] = ssk;
    __syncthreads();
    for (int s2 = 128; s2 > 0; s2 >>= 1) {
        if (tid < s2) red[tid] += red[tid + s2];
        __syncthreads();
    }
    float kscale = rsqrtf(red[0] * (1.0f / KD) + EPSV);
#pragma unroll
    for (int i = 0; i < KD / 256; i++) {
        int idx = tid + i * 256;
        g_k[(size_t)t * KD + idx] = row[idx] * kscale * knw[idx];
    }
}

// ---------------------------------------------------------------------------
// Causal GQA flash attention, fp32, warp-per-query.
// grid(T/8, H), 256 threads (8 warps = 8 consecutive queries of one head).
// 32-key K/V tiles staged in smem, shared by all 8 warps.
// ---------------------------------------------------------------------------
__global__ __launch_bounds__(256) void flash_kernel() {
    __shared__ float Ks[32][128];
    __shared__ float Vs[32][128];

    const int h    = blockIdx.y;
    const int kvh  = h >> 2;           // H/HKV = 4
    const int q0   = blockIdx.x * 8;
    const int warp = threadIdx.x >> 5;
    const int lane = threadIdx.x & 31;
    const int t    = q0 + warp;

    const float* qp = g_q + (size_t)t * QD + h * D;
    const float q0r = qp[lane];
    const float q1r = qp[lane + 32];
    const float q2r = qp[lane + 64];
    const float q3r = qp[lane + 96];

    float m = -1e30f, l = 0.0f;
    float o0 = 0.f, o1 = 0.f, o2 = 0.f, o3 = 0.f;

    const int   ntiles = (q0 + 7) / 32 + 1;
    const float scale  = 0.08838834764831845f;   // 1/sqrt(128)

    for (int tile = 0; tile < ntiles; tile++) {
        const int k0 = tile * 32;
        // cooperative load of 32 keys' K and V rows (128 floats each)
#pragma unroll
        for (int it = 0; it < 4; it++) {
            int idx4 = threadIdx.x + it * 256;   // 0..1023 float4 slots
            int j    = idx4 >> 5;
            int d4   = (idx4 & 31) * 4;
            int key  = k0 + j;
            *(float4*)&Ks[j][d4] =
                *(const float4*)&g_k[(size_t)key * KD + kvh * D + d4];
            *(float4*)&Vs[j][d4] =
                *(const float4*)&g_qkv[(size_t)key * QKV_N + QD + KD + kvh * D + d4];
        }
        __syncthreads();

        const int jmax = min(31, t - k0);        // causal bound (uniform per warp)
        for (int j = 0; j <= jmax; j++) {
            float s = q0r * Ks[j][lane];
            s = fmaf(q1r, Ks[j][lane + 32], s);
            s = fmaf(q2r, Ks[j][lane + 64], s);
            s = fmaf(q3r, Ks[j][lane + 96], s);
#pragma unroll
            for (int off = 16; off; off >>= 1)
                s += __shfl_xor_sync(0xffffffffu, s, off);
            s *= scale;
            float mn   = fmaxf(m, s);
            float corr = __expf(m - mn);
            float p    = __expf(s - mn);
            l = l * corr + p;
            m = mn;
            o0 = o0 * corr + p * Vs[j][lane];
            o1 = o1 * corr + p * Vs[j][lane + 32];
            o2 = o2 * corr + p * Vs[j][lane + 64];
            o3 = o3 * corr + p * Vs[j][lane + 96];
        }
        __syncthreads();
    }

    const float inv = 1.0f / l;
    float* op = g_attn + (size_t)t * QD + h * D;
    op[lane]      = o0 * inv;
    op[lane + 32] = o1 * inv;
    op[lane + 64] = o2 * inv;
    op[lane + 96] = o3 * inv;
}

// ---------------------------------------------------------------------------
// Launch
// ---------------------------------------------------------------------------
extern "C" void kernel_launch(void* const* d_in, const int* in_sizes, int n_in,
                              void* d_out, int out_size) {
    const int*   positions = (const int*)d_in[0];
    const float* hs        = (const float*)d_in[1];
    const float* w_qkv     = (const float*)d_in[2];
    const float* w_o       = (const float*)d_in[3];
    const float* qnw       = (const float*)d_in[4];
    const float* knw       = (const float*)d_in[5];
    float*       out       = (float*)d_out;

    float *qkv_p, *attn_p;
    cudaGetSymbolAddress((void**)&qkv_p, g_qkv);
    cudaGetSymbolAddress((void**)&attn_p, g_attn);

    // 1) QKV projection: [T,HID] x [3072,HID]^T -> [T,3072]
    {
        dim3 grid(QKV_N / 128, T / 128);
        sgemm_nt<<<grid, 256>>>(hs, w_qkv, qkv_p, T, QKV_N, HID);
    }
    // 2) RoPE + RMSNorm
    rope_norm_kernel<<<T, 256>>>(positions, qnw, knw);
    // 3) Causal GQA attention
    {
        dim3 grid(T / 8, H);
        flash_kernel<<<grid, 256>>>();
    }
    // 4) Output projection: [T,2048] x [2048,2048]^T -> [T,2048]
    {
        dim3 grid(HID / 128, T / 128);
        sgemm_nt<<<grid, 256>>>(attn_p, w_o, out, T, HID, QD);
    }
}

// round 2
// speedup vs baseline: 2.1564x; 2.1564x over previous
#include <cuda_runtime.h>
#include <math.h>

#define T     4096
#define H     16
#define HKV   4
#define D     128
#define HID   2048
#define QKV_N ((H + 2 * HKV) * D)   // 3072
#define QD    (H * D)               // 2048
#define KD    (HKV * D)             // 512
#define EPSV  1e-5f

// Scratch (device globals: allocation-free per harness rules)
__device__ float g_qkv[T * QKV_N];   // [T, 3072]  q|k|v projection output
__device__ float g_q[T * QD];        // roped+normed q
__device__ float g_k[T * KD];        // roped+normed k
__device__ float g_attn[T * QD];     // attention output

// ---------------------------------------------------------------------------
// NT SGEMM: C[M,N] = A[M,K] * B[N,K]^T
// ---------------------------------------------------------------------------
__global__ __launch_bounds__(256) void sgemm_nt(const float* __restrict__ A,
                                                const float* __restrict__ B,
                                                float* __restrict__ C,
                                                int M, int N, int K) {
    __shared__ float As[8][128];
    __shared__ float Bs[8][128];

    const int bm  = blockIdx.y * 128;
    const int bn  = blockIdx.x * 128;
    const int tid = threadIdx.x;
    const int tx  = tid % 16;
    const int ty  = tid / 16;

    float acc[8][8];
#pragma unroll
    for (int i = 0; i < 8; i++)
#pragma unroll
        for (int j = 0; j < 8; j++) acc[i][j] = 0.0f;

    const int lr = tid / 2;
    const int lc = (tid % 2) * 4;
    const float* Ap = A + (size_t)(bm + lr) * K + lc;
    const float* Bp = B + (size_t)(bn + lr) * K + lc;

    for (int k0 = 0; k0 < K; k0 += 8) {
        float4 av = *(const float4*)(Ap + k0);
        float4 bv = *(const float4*)(Bp + k0);
        As[lc + 0][lr] = av.x; As[lc + 1][lr] = av.y;
        As[lc + 2][lr] = av.z; As[lc + 3][lr] = av.w;
        Bs[lc + 0][lr] = bv.x; Bs[lc + 1][lr] = bv.y;
        Bs[lc + 2][lr] = bv.z; Bs[lc + 3][lr] = bv.w;
        __syncthreads();

#pragma unroll
        for (int kk = 0; kk < 8; kk++) {
            float a[8], b[8];
            *(float4*)&a[0] = *(const float4*)&As[kk][ty * 8];
            *(float4*)&a[4] = *(const float4*)&As[kk][ty * 8 + 4];
            *(float4*)&b[0] = *(const float4*)&Bs[kk][tx * 8];
            *(float4*)&b[4] = *(const float4*)&Bs[kk][tx * 8 + 4];
#pragma unroll
            for (int i = 0; i < 8; i++)
#pragma unroll
                for (int j = 0; j < 8; j++)
                    acc[i][j] = fmaf(a[i], b[j], acc[i][j]);
        }
        __syncthreads();
    }

#pragma unroll
    for (int i = 0; i < 8; i++) {
        float* Cp = C + (size_t)(bm + ty * 8 + i) * N + bn + tx * 8;
#pragma unroll
        for (int j = 0; j < 8; j++) Cp[j] = acc[i][j];
    }
}

// ---------------------------------------------------------------------------
// RoPE + RMSNorm (one CTA per token). exp2f instead of powf.
// ---------------------------------------------------------------------------
__global__ __launch_bounds__(256) void rope_norm_kernel(
    const int* __restrict__ positions,
    const float* __restrict__ qnw,
    const float* __restrict__ knw) {
    const int t   = blockIdx.x;
    const int tid = threadIdx.x;
    const float pos = (float)positions[t];
    // inv_freq = 10000^(-2fi/128) = 2^(fi * -log2(10000)/64)
    const float cexp = -0.20761871963378895f;  // log2(10000)/64

    __shared__ float row[QD];
    __shared__ float red[256];

    const float* base = g_qkv + (size_t)t * QKV_N;

    float ss = 0.0f;
#pragma unroll
    for (int i = 0; i < QD / 256; i++) {
        int idx = tid + i * 256;
        int d   = idx & 127;
        int hb  = idx - d;
        int fi  = d & 63;
        float ang = pos * exp2f((float)fi * cexp);
        float sv, cv;
        sincosf(ang, &sv, &cv);
        float v;
        if (d < 64) v = base[hb + d] * cv - base[hb + d + 64] * sv;
        else        v = base[hb + d] * cv + base[hb + d - 64] * sv;
        row[idx] = v;
        ss += v * v;
    }
    red[tid] = ss;
    __syncthreads();
    for (int s2 = 128; s2 > 0; s2 >>= 1) {
        if (tid < s2) red[tid] += red[tid + s2];
        __syncthreads();
    }
    float qscale = rsqrtf(red[0] * (1.0f / QD) + EPSV);
#pragma unroll
    for (int i = 0; i < QD / 256; i++) {
        int idx = tid + i * 256;
        g_q[(size_t)t * QD + idx] = row[idx] * qscale * qnw[idx];
    }
    __syncthreads();

    const float* kbase = base + QD;
    float ssk = 0.0f;
#pragma unroll
    for (int i = 0; i < KD / 256; i++) {
        int idx = tid + i * 256;
        int d   = idx & 127;
        int hb  = idx - d;
        int fi  = d & 63;
        float ang = pos * exp2f((float)fi * cexp);
        float sv, cv;
        sincosf(ang, &sv, &cv);
        float v;
        if (d < 64) v = kbase[hb + d] * cv - kbase[hb + d + 64] * sv;
        else        v = kbase[hb + d] * cv + kbase[hb + d - 64] * sv;
        row[idx] = v;
        ssk += v * v;
    }
    red[tid] = ssk;
    __syncthreads();
    for (int s2 = 128; s2 > 0; s2 >>= 1) {
        if (tid < s2) red[tid] += red[tid + s2];
        __syncthreads();
    }
    float kscale = rsqrtf(red[0] * (1.0f / KD) + EPSV);
#pragma unroll
    for (int i = 0; i < KD / 256; i++) {
        int idx = tid + i * 256;
        g_k[(size_t)t * KD + idx] = row[idx] * kscale * knw[idx];
    }
}

// ---------------------------------------------------------------------------
// Block-tiled causal GQA flash attention (fp32, FA2-style).
// CTA: 64 queries x 1 head, 256 threads (16x16 thread grid).
// Key tiles of 64. S = Q K^T via 4x4 register tiles from d-major smem;
// online softmax with 4 shfls per row per tile; O += P V via 4x8 tiles.
// ---------------------------------------------------------------------------
#define PADQ 68
#define PADV 132
#define FLASH_SMEM ((2 * 128 * PADQ + 64 * PADV + 64 * PADQ) * 4)

__global__ __launch_bounds__(256) void flash2() {
    extern __shared__ float sm[];
    float* Qt = sm;                        // [128][PADQ]  d-major
    float* Kt = Qt + 128 * PADQ;           // [128][PADQ]  d-major
    float* Vs = Kt + 128 * PADQ;           // [64][PADV]   key-major
    float* Pt = Vs + 64 * PADV;            // [64][PADQ]   key-major

    const int h    = blockIdx.y;
    const int kvh  = h >> 2;
    const int qb   = gridDim.x - 1 - blockIdx.x;   // heaviest blocks first
    const int q0   = qb * 64;
    const int tid  = threadIdx.x;
    const int tx   = tid & 15;
    const int ty   = tid >> 4;

    // ---- Q fill (transposed, pre-scaled by 1/sqrt(D)) ----
    {
        const int q = tid >> 2;
        const float* src = g_q + (size_t)(q0 + q) * QD + h * D;
        const float sc = 0.08838834764831845f;
#pragma unroll
        for (int i = 0; i < 8; i++) {
            int d4 = (tid & 3) + i * 4;
            float4 v = *(const float4*)(src + d4 * 4);
            Qt[(d4 * 4 + 0) * PADQ + q] = v.x * sc;
            Qt[(d4 * 4 + 1) * PADQ + q] = v.y * sc;
            Qt[(d4 * 4 + 2) * PADQ + q] = v.z * sc;
            Qt[(d4 * 4 + 3) * PADQ + q] = v.w * sc;
        }
    }

    float o[4][8];
    float m[4], l[4];
#pragma unroll
    for (int i = 0; i < 4; i++) {
        m[i] = -1e30f; l[i] = 0.0f;
#pragma unroll
        for (int j = 0; j < 8; j++) o[i][j] = 0.0f;
    }

    const int nt = qb + 1;
    for (int tIdx = 0; tIdx < nt; tIdx++) {
        const int k0 = tIdx * 64;

        // ---- K fill (transposed) ----
        {
            const int key = tid >> 2;
            const float* src = g_k + (size_t)(k0 + key) * KD + kvh * D;
#pragma unroll
            for (int i = 0; i < 8; i++) {
                int d4 = (tid & 3) + i * 4;
                float4 v = *(const float4*)(src + d4 * 4);
                Kt[(d4 * 4 + 0) * PADQ + key] = v.x;
                Kt[(d4 * 4 + 1) * PADQ + key] = v.y;
                Kt[(d4 * 4 + 2) * PADQ + key] = v.z;
                Kt[(d4 * 4 + 3) * PADQ + key] = v.w;
            }
        }
        // ---- V fill (row-major) ----
#pragma unroll
        for (int i = 0; i < 8; i++) {
            int idx = tid + 256 * i;
            int key = idx >> 5, d4 = idx & 31;
            *(float4*)&Vs[key * PADV + d4 * 4] =
                *(const float4*)(g_qkv + (size_t)(k0 + key) * QKV_N + QD + KD +
                                 kvh * D + d4 * 4);
        }
        __syncthreads();

        // ---- S = Q K^T  (4x4 per thread) ----
        float s[4][4];
#pragma unroll
        for (int i = 0; i < 4; i++)
#pragma unroll
            for (int j = 0; j < 4; j++) s[i][j] = 0.0f;

#pragma unroll 4
        for (int k = 0; k < 128; k++) {
            float4 a = *(const float4*)&Qt[k * PADQ + ty * 4];
            float4 b = *(const float4*)&Kt[k * PADQ + tx * 4];
            const float av[4] = {a.x, a.y, a.z, a.w};
            const float bv[4] = {b.x, b.y, b.z, b.w};
#pragma unroll
            for (int i = 0; i < 4; i++)
#pragma unroll
                for (int j = 0; j < 4; j++)
                    s[i][j] = fmaf(av[i], bv[j], s[i][j]);
        }

        // ---- causal mask (diagonal tile only) ----
        if (tIdx == nt - 1) {
#pragma unroll
            for (int i = 0; i < 4; i++)
#pragma unroll
                for (int j = 0; j < 4; j++)
                    if (tx * 4 + j > ty * 4 + i) s[i][j] = -1e30f;
        }

        // ---- online softmax over this 64-key tile ----
#pragma unroll
        for (int i = 0; i < 4; i++) {
            float mx = fmaxf(fmaxf(s[i][0], s[i][1]), fmaxf(s[i][2], s[i][3]));
#pragma unroll
            for (int off = 8; off; off >>= 1)
                mx = fmaxf(mx, __shfl_xor_sync(0xffffffffu, mx, off));
            float mn = fmaxf(m[i], mx);
            float corr = __expf(m[i] - mn);
            m[i] = mn;
            float sum = 0.0f;
#pragma unroll
            for (int j = 0; j < 4; j++) {
                float p = __expf(s[i][j] - mn);
                s[i][j] = p;
                sum += p;
            }
#pragma unroll
            for (int off = 8; off; off >>= 1)
                sum += __shfl_xor_sync(0xffffffffu, sum, off);
            l[i] = l[i] * corr + sum;
#pragma unroll
            for (int j = 0; j < 8; j++) o[i][j] *= corr;
        }

        // ---- stage P (key-major) ----
#pragma unroll
        for (int j = 0; j < 4; j++)
#pragma unroll
            for (int i = 0; i < 4; i++)
                Pt[(tx * 4 + j) * PADQ + ty * 4 + i] = s[i][j];
        __syncthreads();

        // ---- O += P V  (4 rows x 8 dims per thread) ----
#pragma unroll 2
        for (int key = 0; key < 64; key++) {
            float4 a  = *(const float4*)&Pt[key * PADQ + ty * 4];
            float4 v0 = *(const float4*)&Vs[key * PADV + tx * 4];
            float4 v1 = *(const float4*)&Vs[key * PADV + 64 + tx * 4];
            const float av[4] = {a.x, a.y, a.z, a.w};
#pragma unroll
            for (int i = 0; i < 4; i++) {
                o[i][0] = fmaf(av[i], v0.x, o[i][0]);
                o[i][1] = fmaf(av[i], v0.y, o[i][1]);
                o[i][2] = fmaf(av[i], v0.z, o[i][2]);
                o[i][3] = fmaf(av[i], v0.w, o[i][3]);
                o[i][4] = fmaf(av[i], v1.x, o[i][4]);
                o[i][5] = fmaf(av[i], v1.y, o[i][5]);
                o[i][6] = fmaf(av[i], v1.z, o[i][6]);
                o[i][7] = fmaf(av[i], v1.w, o[i][7]);
            }
        }
        __syncthreads();
    }

    // ---- epilogue ----
#pragma unroll
    for (int i = 0; i < 4; i++) {
        float inv = 1.0f / l[i];
        float* dst = g_attn + (size_t)(q0 + ty * 4 + i) * QD + h * D;
#pragma unroll
        for (int j = 0; j < 4; j++) dst[tx * 4 + j]      = o[i][j] * inv;
#pragma unroll
        for (int j = 0; j < 4; j++) dst[64 + tx * 4 + j] = o[i][j + 4] * inv;
    }
}

// ---------------------------------------------------------------------------
// Launch
// ---------------------------------------------------------------------------
extern "C" void kernel_launch(void* const* d_in, const int* in_sizes, int n_in,
                              void* d_out, int out_size) {
    const int*   positions = (const int*)d_in[0];
    const float* hs        = (const float*)d_in[1];
    const float* w_qkv     = (const float*)d_in[2];
    const float* w_o       = (const float*)d_in[3];
    const float* qnw       = (const float*)d_in[4];
    const float* knw       = (const float*)d_in[5];
    float*       out       = (float*)d_out;

    float *qkv_p, *attn_p;
    cudaGetSymbolAddress((void**)&qkv_p, g_qkv);
    cudaGetSymbolAddress((void**)&attn_p, g_attn);

    static bool attr_set = false;
    if (!attr_set) {
        cudaFuncSetAttribute(flash2, cudaFuncAttributeMaxDynamicSharedMemorySize,
                             FLASH_SMEM);
        attr_set = true;
    }

    // 1) QKV projection
    {
        dim3 grid(QKV_N / 128, T / 128);
        sgemm_nt<<<grid, 256>>>(hs, w_qkv, qkv_p, T, QKV_N, HID);
    }
    // 2) RoPE + RMSNorm
    rope_norm_kernel<<<T, 256>>>(positions, qnw, knw);
    // 3) Causal GQA attention
    {
        dim3 grid(T / 64, H);
        flash2<<<grid, 256, FLASH_SMEM>>>();
    }
    // 4) Output projection
    {
        dim3 grid(HID / 128, T / 128);
        sgemm_nt<<<grid, 256>>>(attn_p, w_o, out, T, HID, QD);
    }
}

// round 4
// speedup vs baseline: 3.0392x; 1.4093x over previous
#include <cuda_runtime.h>
#include <cuda_bf16.h>
#include <math.h>
#include <stdint.h>

#define T     4096
#define H     16
#define HKV   4
#define D     128
#define HID   2048
#define QKV_N ((H + 2 * HKV) * D)   // 3072
#define QD    (H * D)               // 2048
#define KD    (HKV * D)             // 512
#define EPSV  1e-5f
#define GK    2048
#define NCHUNK (GK / 32)            // 64 k-chunks of 32 bf16

// fp32 scratch
__device__ float g_qkv[T * QKV_N];
__device__ float g_q[T * QD];
__device__ float g_k[T * KD];
__device__ float g_attn[T * QD];

// bf16 split scratch
__device__ __nv_bfloat16 g_hsh[T * HID],     g_hsl[T * HID];
__device__ __nv_bfloat16 g_wqh[QKV_N * HID], g_wql[QKV_N * HID];
__device__ __nv_bfloat16 g_ath[T * QD],      g_atl[T * QD];
__device__ __nv_bfloat16 g_woh[HID * QD],    g_wol[HID * QD];

// ---------------------------------------------------------------------------
// helpers (sm_80-level PTX only: cp.async, ldmatrix, mma.sync)
// ---------------------------------------------------------------------------
__device__ __forceinline__ uint32_t smem_u32(const void* p) {
    uint32_t a;
    asm("{ .reg .u64 t; cvta.to.shared.u64 t, %1; cvt.u32.u64 %0, t; }"
        : "=r"(a) : "l"(p));
    return a;
}
__device__ __forceinline__ void cp16(uint32_t dst, const void* src) {
    asm volatile("cp.async.cg.shared.global [%0], [%1], 16;"
                 :: "r"(dst), "l"(src));
}
__device__ __forceinline__ void ldsm4(uint32_t* r, uint32_t addr) {
    asm volatile("ldmatrix.sync.aligned.m8n8.x4.shared.b16 {%0,%1,%2,%3}, [%4];"
                 : "=r"(r[0]), "=r"(r[1]), "=r"(r[2]), "=r"(r[3]) : "r"(addr));
}
__device__ __forceinline__ void ldsm2(uint32_t* r, uint32_t addr) {
    asm volatile("ldmatrix.sync.aligned.m8n8.x2.shared.b16 {%0,%1}, [%2];"
                 : "=r"(r[0]), "=r"(r[1]) : "r"(addr));
}
__device__ __forceinline__ void mma16816(float* c, const uint32_t* a,
                                         const uint32_t* b) {
    asm volatile(
        "mma.sync.aligned.m16n8k16.row.col.f32.bf16.bf16.f32 "
        "{%0,%1,%2,%3}, {%4,%5,%6,%7}, {%8,%9}, {%0,%1,%2,%3};"
        : "+f"(c[0]), "+f"(c[1]), "+f"(c[2]), "+f"(c[3])
        : "r"(a[0]), "r"(a[1]), "r"(a[2]), "r"(a[3]), "r"(b[0]), "r"(b[1]));
}

// ---------------------------------------------------------------------------
// fp32 -> (hi, lo) bf16 split
// ---------------------------------------------------------------------------
__global__ __launch_bounds__(256) void split_bf16(const float* __restrict__ x,
                                                  __nv_bfloat16* __restrict__ hi,
                                                  __nv_bfloat16* __restrict__ lo) {
    int idx = blockIdx.x * 256 + threadIdx.x;
    float v = x[idx];
    __nv_bfloat16 h = __float2bfloat16(v);
    hi[idx] = h;
    lo[idx] = __float2bfloat16(v - __bfloat162float(h));
}

// ---------------------------------------------------------------------------
// mma.sync split-bf16 NT GEMM: C[M,N] = A[M,K] B[N,K]^T (fp32 out), K=2048.
// CTA 128x128, BK=32, 8 warps as 2(M)x4(N) -> warp tile 64x32.
// 3-stage cp.async pipeline. Tiles: Ah, Al, Bh, Bl; 3 mma combos per kstep.
// Smem rows padded to 40 bf16 (80B) -> conflict-free ldmatrix.
// ---------------------------------------------------------------------------
#define SA       40
#define TILE_B   (128 * SA * 2)      // 10240 B per tile
#define STAGE_B  (4 * TILE_B)        // 40960 B
#define GSMEM    (3 * STAGE_B)       // 122880 B

__global__ __launch_bounds__(256)
void gemm_tc_mma(const __nv_bfloat16* __restrict__ Ah,
                 const __nv_bfloat16* __restrict__ Al,
                 const __nv_bfloat16* __restrict__ Bh,
                 const __nv_bfloat16* __restrict__ Bl,
                 float* __restrict__ C, int N) {
    extern __shared__ char smem[];
    const uint32_t sbase = smem_u32(smem);
    const int tid  = threadIdx.x;
    const int wid  = tid >> 5;
    const int lane = tid & 31;
    const int wm   = wid & 1;        // 0..1
    const int wn   = wid >> 1;       // 0..3
    const int bm   = blockIdx.y * 128;
    const int bn   = blockIdx.x * 128;

    const __nv_bfloat16* srcs[4];
    srcs[0] = Ah + (size_t)bm * GK;
    srcs[1] = Al + (size_t)bm * GK;
    srcs[2] = Bh + (size_t)bn * GK;
    srcs[3] = Bl + (size_t)bn * GK;

    auto load_chunk = [&](int stage, int k0) {
        uint32_t db = sbase + stage * STAGE_B;
#pragma unroll
        for (int t = 0; t < 4; t++) {
            const __nv_bfloat16* s = srcs[t] + k0;
#pragma unroll
            for (int i = 0; i < 2; i++) {
                int seg = i * 256 + tid;            // 0..511
                int row = seg >> 2, c16 = seg & 3;
                cp16(db + t * TILE_B + row * 80 + c16 * 16,
                     s + (size_t)row * GK + c16 * 8);
            }
        }
        asm volatile("cp.async.commit_group;" ::: "memory");
    };

    float acc[4][4][4];
#pragma unroll
    for (int mt = 0; mt < 4; mt++)
#pragma unroll
        for (int nt = 0; nt < 4; nt++)
#pragma unroll
            for (int r = 0; r < 4; r++) acc[mt][nt][r] = 0.0f;

    load_chunk(0, 0);
    load_chunk(1, 32);

    const int arow  = lane & 15;
    const int akoff = (lane >> 4) * 16;       // 0/16 bytes
    const int brow  = lane & 7;
    const int bkoff = ((lane >> 3) & 1) * 16;

    for (int i = 0; i < NCHUNK; i++) {
        if (i + 2 < NCHUNK)
            asm volatile("cp.async.wait_group 1;" ::: "memory");
        else
            asm volatile("cp.async.wait_group 0;" ::: "memory");
        __syncthreads();

        uint32_t s0 = sbase + (i % 3) * STAGE_B;
        uint32_t aH = s0, aL = s0 + TILE_B;
        uint32_t bH = s0 + 2 * TILE_B, bL = s0 + 3 * TILE_B;

#pragma unroll
        for (int kk = 0; kk < 2; kk++) {
            const int kb = kk * 32;               // byte offset of kstep
            uint32_t ah[4][4], al[4][4], bh[4][2], bl[4][2];
#pragma unroll
            for (int mt = 0; mt < 4; mt++) {
                uint32_t ro = (uint32_t)((wm * 64 + mt * 16 + arow) * 80 + kb + akoff);
                ldsm4(ah[mt], aH + ro);
                ldsm4(al[mt], aL + ro);
            }
#pragma unroll
            for (int nt = 0; nt < 4; nt++) {
                uint32_t ro = (uint32_t)((wn * 32 + nt * 8 + brow) * 80 + kb + bkoff);
                ldsm2(bh[nt], bH + ro);
                ldsm2(bl[nt], bL + ro);
            }
#pragma unroll
            for (int mt = 0; mt < 4; mt++)
#pragma unroll
                for (int nt = 0; nt < 4; nt++) {
                    mma16816(acc[mt][nt], ah[mt], bh[nt]);
                    mma16816(acc[mt][nt], ah[mt], bl[nt]);
                    mma16816(acc[mt][nt], al[mt], bh[nt]);
                }
        }
        __syncthreads();
        if (i + 2 < NCHUNK) load_chunk((i + 2) % 3, (i + 2) * 32);
    }

    // epilogue: direct float2 stores from c-fragments
#pragma unroll
    for (int mt = 0; mt < 4; mt++) {
        const int row0 = bm + wm * 64 + mt * 16 + (lane >> 2);
#pragma unroll
        for (int nt = 0; nt < 4; nt++) {
            const int col = bn + wn * 32 + nt * 8 + (lane & 3) * 2;
            *(float2*)&C[(size_t)row0 * N + col] =
                make_float2(acc[mt][nt][0], acc[mt][nt][1]);
            *(float2*)&C[(size_t)(row0 + 8) * N + col] =
                make_float2(acc[mt][nt][2], acc[mt][nt][3]);
        }
    }
}

// ---------------------------------------------------------------------------
// RoPE + RMSNorm (one CTA per token)
// ---------------------------------------------------------------------------
__global__ __launch_bounds__(256) void rope_norm_kernel(
    const int* __restrict__ positions,
    const float* __restrict__ qnw,
    const float* __restrict__ knw) {
    const int t   = blockIdx.x;
    const int tid = threadIdx.x;
    const float pos  = (float)positions[t];
    const float cexp = -0.20761871963378895f;  // -log2(10000)/64

    __shared__ float row[QD];
    __shared__ float red[256];

    const float* base = g_qkv + (size_t)t * QKV_N;

    float ss = 0.0f;
#pragma unroll
    for (int i = 0; i < QD / 256; i++) {
        int idx = tid + i * 256;
        int d   = idx & 127;
        int hb  = idx - d;
        int fi  = d & 63;
        float ang = pos * exp2f((float)fi * cexp);
        float sv, cv;
        sincosf(ang, &sv, &cv);
        float v;
        if (d < 64) v = base[hb + d] * cv - base[hb + d + 64] * sv;
        else        v = base[hb + d] * cv + base[hb + d - 64] * sv;
        row[idx] = v;
        ss += v * v;
    }
    red[tid] = ss;
    __syncthreads();
    for (int s2 = 128; s2 > 0; s2 >>= 1) {
        if (tid < s2) red[tid] += red[tid + s2];
        __syncthreads();
    }
    float qscale = rsqrtf(red[0] * (1.0f / QD) + EPSV);
#pragma unroll
    for (int i = 0; i < QD / 256; i++) {
        int idx = tid + i * 256;
        g_q[(size_t)t * QD + idx] = row[idx] * qscale * qnw[idx];
    }
    __syncthreads();

    const float* kbase = base + QD;
    float ssk = 0.0f;
#pragma unroll
    for (int i = 0; i < KD / 256; i++) {
        int idx = tid + i * 256;
        int d   = idx & 127;
        int hb  = idx - d;
        int fi  = d & 63;
        float ang = pos * exp2f((float)fi * cexp);
        float sv, cv;
        sincosf(ang, &sv, &cv);
        float v;
        if (d < 64) v = kbase[hb + d] * cv - kbase[hb + d + 64] * sv;
        else        v = kbase[hb + d] * cv + kbase[hb + d - 64] * sv;
        row[idx] = v;
        ssk += v * v;
    }
    red[tid] = ssk;
    __syncthreads();
    for (int s2 = 128; s2 > 0; s2 >>= 1) {
        if (tid < s2) red[tid] += red[tid + s2];
        __syncthreads();
    }
    float kscale = rsqrtf(red[0] * (1.0f / KD) + EPSV);
#pragma unroll
    for (int i = 0; i < KD / 256; i++) {
        int idx = tid + i * 256;
        g_k[(size_t)t * KD + idx] = row[idx] * kscale * knw[idx];
    }
}

// ---------------------------------------------------------------------------
// Block-tiled causal GQA flash attention (fp32, FA2-style). Unchanged.
// ---------------------------------------------------------------------------
#define PADQ 68
#define PADV 132
#define FLASH_SMEM ((2 * 128 * PADQ + 64 * PADV + 64 * PADQ) * 4)

__global__ __launch_bounds__(256) void flash2() {
    extern __shared__ float sm[];
    float* Qt = sm;
    float* Kt = Qt + 128 * PADQ;
    float* Vs = Kt + 128 * PADQ;
    float* Pt = Vs + 64 * PADV;

    const int h   = blockIdx.y;
    const int kvh = h >> 2;
    const int qb  = gridDim.x - 1 - blockIdx.x;
    const int q0  = qb * 64;
    const int tid = threadIdx.x;
    const int tx  = tid & 15;
    const int ty  = tid >> 4;

    {
        const int q = tid >> 2;
        const float* src = g_q + (size_t)(q0 + q) * QD + h * D;
        const float sc = 0.08838834764831845f;
#pragma unroll
        for (int i = 0; i < 8; i++) {
            int d4 = (tid & 3) + i * 4;
            float4 v = *(const float4*)(src + d4 * 4);
            Qt[(d4 * 4 + 0) * PADQ + q] = v.x * sc;
            Qt[(d4 * 4 + 1) * PADQ + q] = v.y * sc;
            Qt[(d4 * 4 + 2) * PADQ + q] = v.z * sc;
            Qt[(d4 * 4 + 3) * PADQ + q] = v.w * sc;
        }
    }

    float o[4][8];
    float m[4], l[4];
#pragma unroll
    for (int i = 0; i < 4; i++) {
        m[i] = -1e30f; l[i] = 0.0f;
#pragma unroll
        for (int j = 0; j < 8; j++) o[i][j] = 0.0f;
    }

    const int nt = qb + 1;
    for (int tIdx = 0; tIdx < nt; tIdx++) {
        const int k0 = tIdx * 64;

        {
            const int key = tid >> 2;
            const float* src = g_k + (size_t)(k0 + key) * KD + kvh * D;
#pragma unroll
            for (int i = 0; i < 8; i++) {
                int d4 = (tid & 3) + i * 4;
                float4 v = *(const float4*)(src + d4 * 4);
                Kt[(d4 * 4 + 0) * PADQ + key] = v.x;
                Kt[(d4 * 4 + 1) * PADQ + key] = v.y;
                Kt[(d4 * 4 + 2) * PADQ + key] = v.z;
                Kt[(d4 * 4 + 3) * PADQ + key] = v.w;
            }
        }
#pragma unroll
        for (int i = 0; i < 8; i++) {
            int idx = tid + 256 * i;
            int key = idx >> 5, d4 = idx & 31;
            *(float4*)&Vs[key * PADV + d4 * 4] =
                *(const float4*)(g_qkv + (size_t)(k0 + key) * QKV_N + QD + KD +
                                 kvh * D + d4 * 4);
        }
        __syncthreads();

        float s[4][4];
#pragma unroll
        for (int i = 0; i < 4; i++)
#pragma unroll
            for (int j = 0; j < 4; j++) s[i][j] = 0.0f;

#pragma unroll 4
        for (int k = 0; k < 128; k++) {
            float4 a = *(const float4*)&Qt[k * PADQ + ty * 4];
            float4 b = *(const float4*)&Kt[k * PADQ + tx * 4];
            const float av[4] = {a.x, a.y, a.z, a.w};
            const float bv[4] = {b.x, b.y, b.z, b.w};
#pragma unroll
            for (int i = 0; i < 4; i++)
#pragma unroll
                for (int j = 0; j < 4; j++)
                    s[i][j] = fmaf(av[i], bv[j], s[i][j]);
        }

        if (tIdx == nt - 1) {
#pragma unroll
            for (int i = 0; i < 4; i++)
#pragma unroll
                for (int j = 0; j < 4; j++)
                    if (tx * 4 + j > ty * 4 + i) s[i][j] = -1e30f;
        }

#pragma unroll
        for (int i = 0; i < 4; i++) {
            float mx = fmaxf(fmaxf(s[i][0], s[i][1]), fmaxf(s[i][2], s[i][3]));
#pragma unroll
            for (int off = 8; off; off >>= 1)
                mx = fmaxf(mx, __shfl_xor_sync(0xffffffffu, mx, off));
            float mn = fmaxf(m[i], mx);
            float corr = __expf(m[i] - mn);
            m[i] = mn;
            float sum = 0.0f;
#pragma unroll
            for (int j = 0; j < 4; j++) {
                float p = __expf(s[i][j] - mn);
                s[i][j] = p;
                sum += p;
            }
#pragma unroll
            for (int off = 8; off; off >>= 1)
                sum += __shfl_xor_sync(0xffffffffu, sum, off);
            l[i] = l[i] * corr + sum;
#pragma unroll
            for (int j = 0; j < 8; j++) o[i][j] *= corr;
        }

#pragma unroll
        for (int j = 0; j < 4; j++)
#pragma unroll
            for (int i = 0; i < 4; i++)
                Pt[(tx * 4 + j) * PADQ + ty * 4 + i] = s[i][j];
        __syncthreads();

#pragma unroll 2
        for (int key = 0; key < 64; key++) {
            float4 a  = *(const float4*)&Pt[key * PADQ + ty * 4];
            float4 v0 = *(const float4*)&Vs[key * PADV + tx * 4];
            float4 v1 = *(const float4*)&Vs[key * PADV + 64 + tx * 4];
            const float av[4] = {a.x, a.y, a.z, a.w};
#pragma unroll
            for (int i = 0; i < 4; i++) {
                o[i][0] = fmaf(av[i], v0.x, o[i][0]);
                o[i][1] = fmaf(av[i], v0.y, o[i][1]);
                o[i][2] = fmaf(av[i], v0.z, o[i][2]);
                o[i][3] = fmaf(av[i], v0.w, o[i][3]);
                o[i][4] = fmaf(av[i], v1.x, o[i][4]);
                o[i][5] = fmaf(av[i], v1.y, o[i][5]);
                o[i][6] = fmaf(av[i], v1.z, o[i][6]);
                o[i][7] = fmaf(av[i], v1.w, o[i][7]);
            }
        }
        __syncthreads();
    }

#pragma unroll
    for (int i = 0; i < 4; i++) {
        float inv = 1.0f / l[i];
        float* dst = g_attn + (size_t)(q0 + ty * 4 + i) * QD + h * D;
#pragma unroll
        for (int j = 0; j < 4; j++) dst[tx * 4 + j]      = o[i][j] * inv;
#pragma unroll
        for (int j = 0; j < 4; j++) dst[64 + tx * 4 + j] = o[i][j + 4] * inv;
    }
}

// ---------------------------------------------------------------------------
// Launch
// ---------------------------------------------------------------------------
extern "C" void kernel_launch(void* const* d_in, const int* in_sizes, int n_in,
                              void* d_out, int out_size) {
    const int*   positions = (const int*)d_in[0];
    const float* hs        = (const float*)d_in[1];
    const float* w_qkv     = (const float*)d_in[2];
    const float* w_o       = (const float*)d_in[3];
    const float* qnw       = (const float*)d_in[4];
    const float* knw       = (const float*)d_in[5];
    float*       out       = (float*)d_out;

    float *qkv_p, *attn_p;
    cudaGetSymbolAddress((void**)&qkv_p, g_qkv);
    cudaGetSymbolAddress((void**)&attn_p, g_attn);

    __nv_bfloat16 *hsh, *hsl, *wqh, *wql, *ath, *atl, *woh, *wol;
    cudaGetSymbolAddress((void**)&hsh, g_hsh);
    cudaGetSymbolAddress((void**)&hsl, g_hsl);
    cudaGetSymbolAddress((void**)&wqh, g_wqh);
    cudaGetSymbolAddress((void**)&wql, g_wql);
    cudaGetSymbolAddress((void**)&ath, g_ath);
    cudaGetSymbolAddress((void**)&atl, g_atl);
    cudaGetSymbolAddress((void**)&woh, g_woh);
    cudaGetSymbolAddress((void**)&wol, g_wol);

    static bool attr_set = false;
    if (!attr_set) {
        cudaFuncSetAttribute(flash2, cudaFuncAttributeMaxDynamicSharedMemorySize,
                             FLASH_SMEM);
        cudaFuncSetAttribute(gemm_tc_mma,
                             cudaFuncAttributeMaxDynamicSharedMemorySize, GSMEM);
        attr_set = true;
    }

    // splits for QKV GEMM
    split_bf16<<<T * HID / 256, 256>>>(hs, hsh, hsl);
    split_bf16<<<QKV_N * HID / 256, 256>>>(w_qkv, wqh, wql);

    // 1) QKV projection (tensor cores via mma.sync)
    {
        dim3 grid(QKV_N / 128, T / 128);
        gemm_tc_mma<<<grid, 256, GSMEM>>>(hsh, hsl, wqh, wql, qkv_p, QKV_N);
    }
    // 2) RoPE + RMSNorm
    rope_norm_kernel<<<T, 256>>>(positions, qnw, knw);
    // 3) Causal GQA attention
    {
        dim3 grid(T / 64, H);
        flash2<<<grid, 256, FLASH_SMEM>>>();
    }
    // 4) Output projection (tensor cores via mma.sync)
    split_bf16<<<T * QD / 256, 256>>>(attn_p, ath, atl);
    split_bf16<<<HID * QD / 256, 256>>>(w_o, woh, wol);
    {
        dim3 grid(HID / 128, T / 128);
        gemm_tc_mma<<<grid, 256, GSMEM>>>(ath, atl, woh, wol, out, HID);
    }
}

// round 5
// speedup vs baseline: 5.7779x; 1.9011x over previous
#include <cuda_runtime.h>
#include <cuda_bf16.h>
#include <math.h>
#include <stdint.h>

#define T     4096
#define H     16
#define HKV   4
#define D     128
#define HID   2048
#define QKV_N ((H + 2 * HKV) * D)   // 3072
#define QD    (H * D)               // 2048
#define KD    (HKV * D)             // 512
#define EPSV  1e-5f
#define GK    2048
#define NCHUNK (GK / 32)

// fp32 scratch
__device__ float g_qkv[T * QKV_N];

// bf16 split scratch
__device__ __nv_bfloat16 g_hsh[T * HID],     g_hsl[T * HID];
__device__ __nv_bfloat16 g_wqh[QKV_N * HID], g_wql[QKV_N * HID];
__device__ __nv_bfloat16 g_woh[HID * QD],    g_wol[HID * QD];
__device__ __nv_bfloat16 g_qh[T * QD],  g_ql[T * QD];
__device__ __nv_bfloat16 g_kh[T * KD],  g_kl[T * KD];
__device__ __nv_bfloat16 g_vh[T * KD],  g_vl[T * KD];
__device__ __nv_bfloat16 g_ath[T * QD], g_atl[T * QD];

// ---------------------------------------------------------------------------
// helpers (sm_80-level PTX only)
// ---------------------------------------------------------------------------
__device__ __forceinline__ uint32_t smem_u32(const void* p) {
    uint32_t a;
    asm("{ .reg .u64 t; cvta.to.shared.u64 t, %1; cvt.u32.u64 %0, t; }"
        : "=r"(a) : "l"(p));
    return a;
}
__device__ __forceinline__ void cp16(uint32_t dst, const void* src) {
    asm volatile("cp.async.cg.shared.global [%0], [%1], 16;"
                 :: "r"(dst), "l"(src));
}
__device__ __forceinline__ void ldsm4(uint32_t* r, uint32_t addr) {
    asm volatile("ldmatrix.sync.aligned.m8n8.x4.shared.b16 {%0,%1,%2,%3}, [%4];"
                 : "=r"(r[0]), "=r"(r[1]), "=r"(r[2]), "=r"(r[3]) : "r"(addr));
}
__device__ __forceinline__ void ldsm4t(uint32_t* r, uint32_t addr) {
    asm volatile("ldmatrix.sync.aligned.m8n8.x4.trans.shared.b16 {%0,%1,%2,%3}, [%4];"
                 : "=r"(r[0]), "=r"(r[1]), "=r"(r[2]), "=r"(r[3]) : "r"(addr));
}
__device__ __forceinline__ void ldsm2(uint32_t* r, uint32_t addr) {
    asm volatile("ldmatrix.sync.aligned.m8n8.x2.shared.b16 {%0,%1}, [%2];"
                 : "=r"(r[0]), "=r"(r[1]) : "r"(addr));
}
__device__ __forceinline__ void mma16816(float* c, const uint32_t* a,
                                         const uint32_t* b) {
    asm volatile(
        "mma.sync.aligned.m16n8k16.row.col.f32.bf16.bf16.f32 "
        "{%0,%1,%2,%3}, {%4,%5,%6,%7}, {%8,%9}, {%0,%1,%2,%3};"
        : "+f"(c[0]), "+f"(c[1]), "+f"(c[2]), "+f"(c[3])
        : "r"(a[0]), "r"(a[1]), "r"(a[2]), "r"(a[3]), "r"(b[0]), "r"(b[1]));
}
__device__ __forceinline__ uint32_t pack_split(float a, float b, uint32_t& lo) {
    __nv_bfloat16 ha = __float2bfloat16(a), hb = __float2bfloat16(b);
    __nv_bfloat162 hi2; hi2.x = ha; hi2.y = hb;
    __nv_bfloat162 lo2;
    lo2.x = __float2bfloat16(a - __bfloat162float(ha));
    lo2.y = __float2bfloat16(b - __bfloat162float(hb));
    lo = *(uint32_t*)&lo2;
    return *(uint32_t*)&hi2;
}

// ---------------------------------------------------------------------------
// fp32 -> (hi, lo) bf16 split
// ---------------------------------------------------------------------------
__global__ __launch_bounds__(256) void split_bf16(const float* __restrict__ x,
                                                  __nv_bfloat16* __restrict__ hi,
                                                  __nv_bfloat16* __restrict__ lo) {
    int idx = blockIdx.x * 256 + threadIdx.x;
    float v = x[idx];
    __nv_bfloat16 h = __float2bfloat16(v);
    hi[idx] = h;
    lo[idx] = __float2bfloat16(v - __bfloat162float(h));
}

// ---------------------------------------------------------------------------
// mma.sync split-bf16 NT GEMM (unchanged from round 4)
// ---------------------------------------------------------------------------
#define SA       40
#define TILE_B   (128 * SA * 2)
#define STAGE_B  (4 * TILE_B)
#define GSMEM    (3 * STAGE_B)

__global__ __launch_bounds__(256)
void gemm_tc_mma(const __nv_bfloat16* __restrict__ Ah,
                 const __nv_bfloat16* __restrict__ Al,
                 const __nv_bfloat16* __restrict__ Bh,
                 const __nv_bfloat16* __restrict__ Bl,
                 float* __restrict__ C, int N) {
    extern __shared__ char smem[];
    const uint32_t sbase = smem_u32(smem);
    const int tid  = threadIdx.x;
    const int wid  = tid >> 5;
    const int lane = tid & 31;
    const int wm   = wid & 1;
    const int wn   = wid >> 1;
    const int bm   = blockIdx.y * 128;
    const int bn   = blockIdx.x * 128;

    const __nv_bfloat16* srcs[4];
    srcs[0] = Ah + (size_t)bm * GK;
    srcs[1] = Al + (size_t)bm * GK;
    srcs[2] = Bh + (size_t)bn * GK;
    srcs[3] = Bl + (size_t)bn * GK;

    auto load_chunk = [&](int stage, int k0) {
        uint32_t db = sbase + stage * STAGE_B;
#pragma unroll
        for (int t = 0; t < 4; t++) {
            const __nv_bfloat16* s = srcs[t] + k0;
#pragma unroll
            for (int i = 0; i < 2; i++) {
                int seg = i * 256 + tid;
                int row = seg >> 2, c16 = seg & 3;
                cp16(db + t * TILE_B + row * 80 + c16 * 16,
                     s + (size_t)row * GK + c16 * 8);
            }
        }
        asm volatile("cp.async.commit_group;" ::: "memory");
    };

    float acc[4][4][4];
#pragma unroll
    for (int mt = 0; mt < 4; mt++)
#pragma unroll
        for (int nt = 0; nt < 4; nt++)
#pragma unroll
            for (int r = 0; r < 4; r++) acc[mt][nt][r] = 0.0f;

    load_chunk(0, 0);
    load_chunk(1, 32);

    const int arow  = lane & 15;
    const int akoff = (lane >> 4) * 16;
    const int brow  = lane & 7;
    const int bkoff = ((lane >> 3) & 1) * 16;

    for (int i = 0; i < NCHUNK; i++) {
        if (i + 2 < NCHUNK)
            asm volatile("cp.async.wait_group 1;" ::: "memory");
        else
            asm volatile("cp.async.wait_group 0;" ::: "memory");
        __syncthreads();

        uint32_t s0 = sbase + (i % 3) * STAGE_B;
        uint32_t aH = s0, aL = s0 + TILE_B;
        uint32_t bH = s0 + 2 * TILE_B, bL = s0 + 3 * TILE_B;

#pragma unroll
        for (int kk = 0; kk < 2; kk++) {
            const int kb = kk * 32;
            uint32_t ah[4][4], al[4][4], bh[4][2], bl[4][2];
#pragma unroll
            for (int mt = 0; mt < 4; mt++) {
                uint32_t ro = (uint32_t)((wm * 64 + mt * 16 + arow) * 80 + kb + akoff);
                ldsm4(ah[mt], aH + ro);
                ldsm4(al[mt], aL + ro);
            }
#pragma unroll
            for (int nt = 0; nt < 4; nt++) {
                uint32_t ro = (uint32_t)((wn * 32 + nt * 8 + brow) * 80 + kb + bkoff);
                ldsm2(bh[nt], bH + ro);
                ldsm2(bl[nt], bL + ro);
            }
#pragma unroll
            for (int mt = 0; mt < 4; mt++)
#pragma unroll
                for (int nt = 0; nt < 4; nt++) {
                    mma16816(acc[mt][nt], ah[mt], bh[nt]);
                    mma16816(acc[mt][nt], ah[mt], bl[nt]);
                    mma16816(acc[mt][nt], al[mt], bh[nt]);
                }
        }
        __syncthreads();
        if (i + 2 < NCHUNK) load_chunk((i + 2) % 3, (i + 2) * 32);
    }

#pragma unroll
    for (int mt = 0; mt < 4; mt++) {
        const int row0 = bm + wm * 64 + mt * 16 + (lane >> 2);
#pragma unroll
        for (int nt = 0; nt < 4; nt++) {
            const int col = bn + wn * 32 + nt * 8 + (lane & 3) * 2;
            *(float2*)&C[(size_t)row0 * N + col] =
                make_float2(acc[mt][nt][0], acc[mt][nt][1]);
            *(float2*)&C[(size_t)(row0 + 8) * N + col] =
                make_float2(acc[mt][nt][2], acc[mt][nt][3]);
        }
    }
}

// ---------------------------------------------------------------------------
// RoPE + RMSNorm; emits split-bf16 q, k, v.
// ---------------------------------------------------------------------------
__global__ __launch_bounds__(256) void rope_norm_kernel(
    const int* __restrict__ positions,
    const float* __restrict__ qnw,
    const float* __restrict__ knw) {
    const int t   = blockIdx.x;
    const int tid = threadIdx.x;
    const float pos  = (float)positions[t];
    const float cexp = -0.20761871963378895f;  // -log2(10000)/64

    __shared__ float row[QD];
    __shared__ float red[256];

    const float* base = g_qkv + (size_t)t * QKV_N;

    float ss = 0.0f;
#pragma unroll
    for (int i = 0; i < QD / 256; i++) {
        int idx = tid + i * 256;
        int d   = idx & 127;
        int hb  = idx - d;
        int fi  = d & 63;
        float ang = pos * exp2f((float)fi * cexp);
        float sv, cv;
        sincosf(ang, &sv, &cv);
        float v;
        if (d < 64) v = base[hb + d] * cv - base[hb + d + 64] * sv;
        else        v = base[hb + d] * cv + base[hb + d - 64] * sv;
        row[idx] = v;
        ss += v * v;
    }
    red[tid] = ss;
    __syncthreads();
    for (int s2 = 128; s2 > 0; s2 >>= 1) {
        if (tid < s2) red[tid] += red[tid + s2];
        __syncthreads();
    }
    float qscale = rsqrtf(red[0] * (1.0f / QD) + EPSV);
#pragma unroll
    for (int i = 0; i < QD / 256; i++) {
        int idx = tid + i * 256;
        float v = row[idx] * qscale * qnw[idx];
        __nv_bfloat16 h = __float2bfloat16(v);
        g_qh[(size_t)t * QD + idx] = h;
        g_ql[(size_t)t * QD + idx] = __float2bfloat16(v - __bfloat162float(h));
    }
    __syncthreads();

    const float* kbase = base + QD;
    float ssk = 0.0f;
#pragma unroll
    for (int i = 0; i < KD / 256; i++) {
        int idx = tid + i * 256;
        int d   = idx & 127;
        int hb  = idx - d;
        int fi  = d & 63;
        float ang = pos * exp2f((float)fi * cexp);
        float sv, cv;
        sincosf(ang, &sv, &cv);
        float v;
        if (d < 64) v = kbase[hb + d] * cv - kbase[hb + d + 64] * sv;
        else        v = kbase[hb + d] * cv + kbase[hb + d - 64] * sv;
        row[idx] = v;
        ssk += v * v;
    }
    red[tid] = ssk;
    __syncthreads();
    for (int s2 = 128; s2 > 0; s2 >>= 1) {
        if (tid < s2) red[tid] += red[tid + s2];
        __syncthreads();
    }
    float kscale = rsqrtf(red[0] * (1.0f / KD) + EPSV);
#pragma unroll
    for (int i = 0; i < KD / 256; i++) {
        int idx = tid + i * 256;
        float v = row[idx] * kscale * knw[idx];
        __nv_bfloat16 h = __float2bfloat16(v);
        g_kh[(size_t)t * KD + idx] = h;
        g_kl[(size_t)t * KD + idx] = __float2bfloat16(v - __bfloat162float(h));
    }
    // v split (no norm)
    const float* vbase = base + QD + KD;
#pragma unroll
    for (int i = 0; i < KD / 256; i++) {
        int idx = tid + i * 256;
        float v = vbase[idx];
        __nv_bfloat16 h = __float2bfloat16(v);
        g_vh[(size_t)t * KD + idx] = h;
        g_vl[(size_t)t * KD + idx] = __float2bfloat16(v - __bfloat162float(h));
    }
}

// ---------------------------------------------------------------------------
// flash_mma: causal GQA attention on tensor cores (split bf16, 3-term).
// CTA: 128 queries x 1 head, 256 threads (8 warps x 16 rows).
// 64-key tiles, double-buffered cp.async. Output: split bf16 g_ath/g_atl.
// ---------------------------------------------------------------------------
#define KVS     272                       // padded row stride (bytes)
#define QSMEM   (128 * KVS)               // 34816
#define KVTILE  (64 * KVS)                // 17408
#define KVSTAGE (4 * KVTILE)              // 69632
#define FSMEM   (2 * QSMEM + 2 * KVSTAGE) // 208896

__global__ __launch_bounds__(256) void flash_mma() {
    extern __shared__ char smem[];
    const uint32_t sbase = smem_u32(smem);
    const int tid  = threadIdx.x;
    const int w    = tid >> 5;
    const int lane = tid & 31;
    const int h    = blockIdx.y;
    const int kvh  = h >> 2;
    const int qb   = (int)gridDim.x - 1 - (int)blockIdx.x;
    const int q0   = qb * 128;
    const int ntiles = 2 * qb + 2;

    // Q load (both splits)
    {
        const __nv_bfloat16* s0 = g_qh + (size_t)q0 * QD + h * D;
        const __nv_bfloat16* s1 = g_ql + (size_t)q0 * QD + h * D;
#pragma unroll
        for (int i = 0; i < 8; i++) {
            int seg = i * 256 + tid;           // 0..2047
            int row = seg >> 4, c = seg & 15;
            cp16(sbase + row * KVS + c * 16, s0 + (size_t)row * QD + c * 8);
            cp16(sbase + QSMEM + row * KVS + c * 16, s1 + (size_t)row * QD + c * 8);
        }
        asm volatile("cp.async.commit_group;" ::: "memory");
    }

    auto load_kv = [&](int stage, int k0) {
        const __nv_bfloat16* srcs[4] = {
            g_kh + (size_t)k0 * KD + kvh * D, g_kl + (size_t)k0 * KD + kvh * D,
            g_vh + (size_t)k0 * KD + kvh * D, g_vl + (size_t)k0 * KD + kvh * D};
        uint32_t db = sbase + 2 * QSMEM + stage * KVSTAGE;
#pragma unroll
        for (int t = 0; t < 4; t++) {
#pragma unroll
            for (int i = 0; i < 4; i++) {
                int seg = i * 256 + tid;       // 0..1023
                int row = seg >> 4, c = seg & 15;
                cp16(db + t * KVTILE + row * KVS + c * 16,
                     srcs[t] + (size_t)row * KD + c * 8);
            }
        }
        asm volatile("cp.async.commit_group;" ::: "memory");
    };

    load_kv(0, 0);

    float o[16][4];
#pragma unroll
    for (int nt = 0; nt < 16; nt++)
#pragma unroll
        for (int r = 0; r < 4; r++) o[nt][r] = 0.0f;
    float m_lo = -1e30f, m_hi = -1e30f, l_lo = 0.0f, l_hi = 0.0f;

    const float scale = 0.08838834764831845f;
    // precomputed lane offsets
    const uint32_t q_off = (uint32_t)((w * 16 + (lane & 15)) * KVS + (lane >> 4) * 16);
    const uint32_t k_off = (uint32_t)((((lane >> 4) << 3) + (lane & 7)) * KVS +
                                      ((lane >> 3) & 1) * 16);
    const uint32_t v_off = (uint32_t)(((((lane >> 3) & 1) << 3) + (lane & 7)) * KVS +
                                      (lane >> 4) * 16);
    const int r_lo = q0 + w * 16 + (lane >> 2);
    const int r_hi = r_lo + 8;

    for (int it = 0; it < ntiles; it++) {
        const int k0 = it * 64;
        if (it + 1 < ntiles) {
            load_kv((it + 1) & 1, (it + 1) * 64);
            asm volatile("cp.async.wait_group 1;" ::: "memory");
        } else {
            asm volatile("cp.async.wait_group 0;" ::: "memory");
        }
        __syncthreads();

        if (k0 <= q0 + w * 16 + 15) {          // warp not fully masked
            const uint32_t kb = sbase + 2 * QSMEM + (it & 1) * KVSTAGE;

            // ---- S = scale * Q K^T (3-term split) ----
            float s[8][4];
#pragma unroll
            for (int nt = 0; nt < 8; nt++)
#pragma unroll
                for (int r = 0; r < 4; r++) s[nt][r] = 0.0f;

#pragma unroll
            for (int kk = 0; kk < 8; kk++) {
                uint32_t aH[4], aL[4];
                uint32_t qa = sbase + q_off + kk * 32;
                ldsm4(aH, qa);
                ldsm4(aL, qa + QSMEM);
#pragma unroll
                for (int np = 0; np < 4; np++) {
                    uint32_t bH[4], bL[4];
                    uint32_t ka = kb + k_off + np * 16 * KVS + kk * 32;
                    ldsm4(bH, ka);
                    ldsm4(bL, ka + KVTILE);
                    mma16816(s[2 * np],     aH, &bH[0]);
                    mma16816(s[2 * np + 1], aH, &bH[2]);
                    mma16816(s[2 * np],     aH, &bL[0]);
                    mma16816(s[2 * np + 1], aH, &bL[2]);
                    mma16816(s[2 * np],     aL, &bH[0]);
                    mma16816(s[2 * np + 1], aL, &bH[2]);
                }
            }

            // ---- scale + causal mask ----
#pragma unroll
            for (int nt = 0; nt < 8; nt++)
#pragma unroll
                for (int r = 0; r < 4; r++) s[nt][r] *= scale;
            if (k0 + 63 > q0) {
#pragma unroll
                for (int nt = 0; nt < 8; nt++) {
#pragma unroll
                    for (int c = 0; c < 2; c++) {
                        int key = k0 + nt * 8 + (lane & 3) * 2 + c;
                        if (key > r_lo) s[nt][c]     = -1e30f;
                        if (key > r_hi) s[nt][2 + c] = -1e30f;
                    }
                }
            }

            // ---- online softmax ----
            float mx_lo = -1e30f, mx_hi = -1e30f;
#pragma unroll
            for (int nt = 0; nt < 8; nt++) {
                mx_lo = fmaxf(mx_lo, fmaxf(s[nt][0], s[nt][1]));
                mx_hi = fmaxf(mx_hi, fmaxf(s[nt][2], s[nt][3]));
            }
            mx_lo = fmaxf(mx_lo, __shfl_xor_sync(0xffffffffu, mx_lo, 1));
            mx_lo = fmaxf(mx_lo, __shfl_xor_sync(0xffffffffu, mx_lo, 2));
            mx_hi = fmaxf(mx_hi, __shfl_xor_sync(0xffffffffu, mx_hi, 1));
            mx_hi = fmaxf(mx_hi, __shfl_xor_sync(0xffffffffu, mx_hi, 2));
            float mn_lo = fmaxf(m_lo, mx_lo);
            float mn_hi = fmaxf(m_hi, mx_hi);
            float cr_lo = __expf(m_lo - mn_lo);
            float cr_hi = __expf(m_hi - mn_hi);
            m_lo = mn_lo; m_hi = mn_hi;

            uint32_t ph2[8][2], pl2[8][2];
            float sum_lo = 0.0f, sum_hi = 0.0f;
#pragma unroll
            for (int nt = 0; nt < 8; nt++) {
                float p0 = __expf(s[nt][0] - m_lo);
                float p1 = __expf(s[nt][1] - m_lo);
                float p2 = __expf(s[nt][2] - m_hi);
                float p3 = __expf(s[nt][3] - m_hi);
                sum_lo += p0 + p1;
                sum_hi += p2 + p3;
                ph2[nt][0] = pack_split(p0, p1, pl2[nt][0]);
                ph2[nt][1] = pack_split(p2, p3, pl2[nt][1]);
            }
            sum_lo += __shfl_xor_sync(0xffffffffu, sum_lo, 1);
            sum_lo += __shfl_xor_sync(0xffffffffu, sum_lo, 2);
            sum_hi += __shfl_xor_sync(0xffffffffu, sum_hi, 1);
            sum_hi += __shfl_xor_sync(0xffffffffu, sum_hi, 2);
            l_lo = l_lo * cr_lo + sum_lo;
            l_hi = l_hi * cr_hi + sum_hi;
#pragma unroll
            for (int nt = 0; nt < 16; nt++) {
                o[nt][0] *= cr_lo; o[nt][1] *= cr_lo;
                o[nt][2] *= cr_hi; o[nt][3] *= cr_hi;
            }

            // ---- O += P V (3-term split) ----
            const uint32_t vb = kb + 2 * KVTILE;
#pragma unroll
            for (int kk = 0; kk < 4; kk++) {
                uint32_t paH[4] = {ph2[2 * kk][0], ph2[2 * kk][1],
                                   ph2[2 * kk + 1][0], ph2[2 * kk + 1][1]};
                uint32_t paL[4] = {pl2[2 * kk][0], pl2[2 * kk][1],
                                   pl2[2 * kk + 1][0], pl2[2 * kk + 1][1]};
#pragma unroll
                for (int nd = 0; nd < 8; nd++) {
                    uint32_t vH[4], vL[4];
                    uint32_t va = vb + v_off + kk * 16 * KVS + nd * 32;
                    ldsm4t(vH, va);
                    ldsm4t(vL, va + KVTILE);
                    mma16816(o[2 * nd],     paH, &vH[0]);
                    mma16816(o[2 * nd + 1], paH, &vH[2]);
                    mma16816(o[2 * nd],     paH, &vL[0]);
                    mma16816(o[2 * nd + 1], paH, &vL[2]);
                    mma16816(o[2 * nd],     paL, &vH[0]);
                    mma16816(o[2 * nd + 1], paL, &vH[2]);
                }
            }
        }
        __syncthreads();
    }

    // ---- epilogue: split-bf16 attn output ----
    const float inv_lo = 1.0f / l_lo;
    const float inv_hi = 1.0f / l_hi;
#pragma unroll
    for (int nt = 0; nt < 16; nt++) {
        int col = h * D + nt * 8 + (lane & 3) * 2;
        uint32_t lo0, lo1;
        uint32_t hi0 = pack_split(o[nt][0] * inv_lo, o[nt][1] * inv_lo, lo0);
        uint32_t hi1 = pack_split(o[nt][2] * inv_hi, o[nt][3] * inv_hi, lo1);
        *(uint32_t*)&g_ath[(size_t)r_lo * QD + col] = hi0;
        *(uint32_t*)&g_atl[(size_t)r_lo * QD + col] = lo0;
        *(uint32_t*)&g_ath[(size_t)r_hi * QD + col] = hi1;
        *(uint32_t*)&g_atl[(size_t)r_hi * QD + col] = lo1;
    }
}

// ---------------------------------------------------------------------------
// Launch
// ---------------------------------------------------------------------------
extern "C" void kernel_launch(void* const* d_in, const int* in_sizes, int n_in,
                              void* d_out, int out_size) {
    const int*   positions = (const int*)d_in[0];
    const float* hs        = (const float*)d_in[1];
    const float* w_qkv     = (const float*)d_in[2];
    const float* w_o       = (const float*)d_in[3];
    const float* qnw       = (const float*)d_in[4];
    const float* knw       = (const float*)d_in[5];
    float*       out       = (float*)d_out;

    float* qkv_p;
    cudaGetSymbolAddress((void**)&qkv_p, g_qkv);

    __nv_bfloat16 *hsh, *hsl, *wqh, *wql, *woh, *wol, *ath, *atl;
    cudaGetSymbolAddress((void**)&hsh, g_hsh);
    cudaGetSymbolAddress((void**)&hsl, g_hsl);
    cudaGetSymbolAddress((void**)&wqh, g_wqh);
    cudaGetSymbolAddress((void**)&wql, g_wql);
    cudaGetSymbolAddress((void**)&woh, g_woh);
    cudaGetSymbolAddress((void**)&wol, g_wol);
    cudaGetSymbolAddress((void**)&ath, g_ath);
    cudaGetSymbolAddress((void**)&atl, g_atl);

    static bool attr_set = false;
    if (!attr_set) {
        cudaFuncSetAttribute(gemm_tc_mma,
                             cudaFuncAttributeMaxDynamicSharedMemorySize, GSMEM);
        cudaFuncSetAttribute(flash_mma,
                             cudaFuncAttributeMaxDynamicSharedMemorySize, FSMEM);
        attr_set = true;
    }

    // splits for QKV GEMM
    split_bf16<<<T * HID / 256, 256>>>(hs, hsh, hsl);
    split_bf16<<<QKV_N * HID / 256, 256>>>(w_qkv, wqh, wql);

    // 1) QKV projection
    {
        dim3 grid(QKV_N / 128, T / 128);
        gemm_tc_mma<<<grid, 256, GSMEM>>>(hsh, hsl, wqh, wql, qkv_p, QKV_N);
    }
    // 2) RoPE + RMSNorm (emits split-bf16 q/k/v)
    rope_norm_kernel<<<T, 256>>>(positions, qnw, knw);
    // 3) Causal GQA attention on tensor cores (emits split-bf16 attn)
    {
        dim3 grid(T / 128, H);
        flash_mma<<<grid, 256, FSMEM>>>();
    }
    // 4) Output projection
    split_bf16<<<HID * QD / 256, 256>>>(w_o, woh, wol);
    {
        dim3 grid(HID / 128, T / 128);
        gemm_tc_mma<<<grid, 256, GSMEM>>>(ath, atl, woh, wol, out, HID);
    }
}